// round 12
// baseline (speedup 1.0000x reference)
#include <cuda_runtime.h>
#include <cuda_fp16.h>

// B=64, T=1000, C=64, F=5, G=2, H=160, 4H=640, D=320, M=B*T=64000

// ---------------- static device scratch ----------------
__device__ __half  g_xT[20480000];     // [D=320][M=64000] k-major GEMM A
__device__ __half  g_out1h[20480000];  // [M][320] stage-1 hidden (fp16)
__device__ float   g_xproj[81920000];  // [M][1280] gate preacts (x@Wih + b), fp32
__device__ __half2 g_wh2[204800];      // [stage][g][80][640] pair-packed Whh: (W[2q][p],W[2q+1][p])
__device__ __half  g_wih[409600];      // [stage][g][160][640] fp16 Wih

// ---------------- helpers ----------------
__device__ __forceinline__ unsigned smem_u32(const void* p) {
    unsigned r;
    asm("{ .reg .u64 t; cvta.to.shared.u64 t, %1; cvt.u32.u64 %0, t; }" : "=r"(r) : "l"(p));
    return r;
}

__device__ __forceinline__ float tanh_ap(float x) {
    float r;
    asm("tanh.approx.f32 %0, %1;" : "=f"(r) : "f"(x));
    return r;
}

#define LDSM_X4T(r0,r1,r2,r3,a) \
    asm volatile("ldmatrix.sync.aligned.m8n8.x4.trans.shared.b16 {%0,%1,%2,%3}, [%4];" \
        : "=r"(r0),"=r"(r1),"=r"(r2),"=r"(r3) : "r"(a))

#define MMA16816(c0,c1,c2,c3,a0,a1,a2,a3,b0,b1) \
    asm volatile("mma.sync.aligned.m16n8k16.row.col.f32.f16.f16.f32 " \
        "{%0,%1,%2,%3}, {%4,%5,%6,%7}, {%8,%9}, {%0,%1,%2,%3};" \
        : "+f"(c0),"+f"(c1),"+f"(c2),"+f"(c3) \
        : "r"(a0),"r"(a1),"r"(a2),"r"(a3),"r"(b0),"r"(b1))

// ---------------- weight convert fp32 -> fp16 ----------------
// v5 packing: thread p owns gate column p; pairs (W[2q][p], W[2q+1][p]).
__global__ void k_convert(const float* __restrict__ Wi1, const float* __restrict__ Wi2,
                          const float* __restrict__ Wh1, const float* __restrict__ Wh2) {
    int i = blockIdx.x * blockDim.x + threadIdx.x;
    if (i >= 409600) return;
    if (i < 204800) g_wih[i] = __float2half(Wi1[i]);
    else            g_wih[i] = __float2half(Wi2[i - 204800]);
    if (i < 204800) {
        int st = i / 102400, r = i - st * 102400;   // per stage: g*51200 + q*640 + p
        int gg = r / 51200,  r2 = r - gg * 51200;
        int q = r2 / 640,    p = r2 - q * 640;
        const float* W = st ? Wh2 : Wh1;
        float a = W[gg * 102400 + (2 * q) * 640 + p];
        float b = W[gg * 102400 + (2 * q + 1) * 640 + p];
        g_wh2[i] = __halves2half2(__float2half(a), __float2half(b));
    }
}

// ---------------- transpose: input[B,C,T,F] -> g_xT[d][m] fp16 ----------------
__global__ __launch_bounds__(256) void k_transpose(const float* __restrict__ inp) {
    __shared__ __half sT[50 * 322];
    int b = blockIdx.x, t0 = blockIdx.y * 50;
    int tid = threadIdx.x;
    for (int i = tid; i < 8000; i += 256) {
        int ch = i / 125, j = i % 125;
        float2 v = *(const float2*)(inp + (size_t)(b * 64 + ch) * 5000 + t0 * 5 + j * 2);
        int e0 = j * 2, e1 = e0 + 1;
        sT[(e0 / 5) * 322 + ch * 5 + (e0 % 5)] = __float2half(v.x);
        sT[(e1 / 5) * 322 + ch * 5 + (e1 % 5)] = __float2half(v.y);
    }
    __syncthreads();
    for (int i = tid; i < 16000; i += 256) {
        int d = i / 50, t = i % 50;
        g_xT[(size_t)d * 64000 + (size_t)b * 1000 + t0 + t] = sT[t * 322 + d];
    }
}

// ---------------- gather: g_xT[d'][m] = out1h[m][snd[d']] ----------------
__global__ __launch_bounds__(256) void k_gather(const int* __restrict__ snd) {
    __shared__ __half sT[64 * 322];
    __shared__ int ssnd[320];
    int m0 = blockIdx.x * 64;
    int tid = threadIdx.x;
    for (int c = tid; c < 2560; c += 256) {
        int m = c / 40, ch = c % 40;
        uint4 v = *(const uint4*)(g_out1h + (size_t)(m0 + m) * 320 + ch * 8);
        unsigned* dst = (unsigned*)(sT + m * 322 + ch * 8);
        dst[0] = v.x; dst[1] = v.y; dst[2] = v.z; dst[3] = v.w;
    }
    for (int i = tid; i < 320; i += 256) ssnd[i] = snd[i];
    __syncthreads();
    for (int i = tid; i < 20480; i += 256) {
        int d = i / 64, m = i % 64;
        g_xT[(size_t)d * 64000 + m0 + m] = sT[m * 322 + ssnd[d]];
    }
}

// ---------------- tensor-core xproj GEMM ----------------
#define GEMM_SMEM (40960 + 102400)
__global__ __launch_bounds__(256) void k_gemm(int stage, const float* __restrict__ bias) {
    int g = blockIdx.z, nb = blockIdx.y * 320, m0 = blockIdx.x * 128;
    extern __shared__ __half gs[];
    __half* sA = gs;            // [160][128] halves, swizzled
    __half* sB = gs + 20480;    // [160][320] halves, swizzled
    unsigned sAu = smem_u32(sA), sBu = smem_u32(sB);
    int tid = threadIdx.x;
    const __half* Ag = g_xT + (size_t)g * 160 * 64000;
    const __half* Wg = g_wih + (size_t)stage * 204800 + (size_t)g * 102400;
    for (int c = tid; c < 2560; c += 256) {
        int k = c >> 4, cm = c & 15;
        uint4 v = *(const uint4*)(Ag + (size_t)k * 64000 + m0 + cm * 8);
        *(uint4*)((char*)sA + k * 256 + ((cm ^ (k & 7)) << 4)) = v;
    }
    for (int c = tid; c < 6400; c += 256) {
        int k = c / 40, ch = c % 40;
        uint4 v = *(const uint4*)(Wg + (size_t)k * 640 + nb + ch * 8);
        *(uint4*)((char*)sB + k * 640 + ((ch ^ (k & 7)) << 4)) = v;
    }
    __syncthreads();

    int w = tid >> 5, l = tid & 31;
    unsigned aAddr = sAu + ((l & 7) + ((l >> 4) << 3)) * 256
                         + (((w * 2 + ((l >> 3) & 1)) ^ (l & 7)) << 4);
    unsigned bRow = sBu + (l & 15) * 640;
    int bl = l & 7, bhi = l >> 4;

    for (int it = 0; it < 10; it++) {
        float acc[16];
#pragma unroll
        for (int i = 0; i < 16; i++) acc[i] = 0.f;
#pragma unroll
        for (int ks = 0; ks < 10; ks++) {
            unsigned a0, a1, a2, a3, b0, b1, b2, b3, b4, b5, b6, b7;
            LDSM_X4T(a0, a1, a2, a3, aAddr + ks * 16 * 256);
            int c0 = it * 4 + bhi;
            LDSM_X4T(b0, b1, b2, b3, bRow + ks * 16 * 640 + ((c0 ^ bl) << 4));
            int c1 = it * 4 + 2 + bhi;
            LDSM_X4T(b4, b5, b6, b7, bRow + ks * 16 * 640 + ((c1 ^ bl) << 4));
            MMA16816(acc[0], acc[1], acc[2], acc[3],  a0, a1, a2, a3, b0, b1);
            MMA16816(acc[4], acc[5], acc[6], acc[7],  a0, a1, a2, a3, b2, b3);
            MMA16816(acc[8], acc[9], acc[10], acc[11], a0, a1, a2, a3, b4, b5);
            MMA16816(acc[12], acc[13], acc[14], acc[15], a0, a1, a2, a3, b6, b7);
        }
        int row0 = m0 + w * 16 + (l >> 2);
        int col = g * 640 + nb + it * 32 + (l & 3) * 2;
#pragma unroll
        for (int ch = 0; ch < 4; ch++) {
            int c = col + ch * 8;
            float2 bv = *(const float2*)(bias + c);
            float2 v0 = { acc[ch * 4 + 0] + bv.x, acc[ch * 4 + 1] + bv.y };
            float2 v1 = { acc[ch * 4 + 2] + bv.x, acc[ch * 4 + 3] + bv.y };
            *(float2*)(g_xproj + (size_t)row0 * 1280 + c) = v0;
            *(float2*)(g_xproj + (size_t)(row0 + 8) * 1280 + c) = v1;
        }
    }
}

// ---------------- persistent recurrent LSTM (v7) ----------------
// grid (64 b, 2 g), 640 threads; thread p owns gate column p, ALL 160 rows.
// ALL 80 weight pairs live in registers (rw[80]) — no weight smem traffic
// in the loop. h packed half[160] broadcast via 20 LDS.128. Owner-only
// activation (5 warps) using MUFU.TANH.

// k-iter uses h-rows 8k..8k+7 (1 broadcast LDS.128) and reg pairs 4k..4k+3.
#define ACC(k) { \
    uint4 hv = sH4[(k)]; \
    const __half2* hp = (const __half2*)&hv; \
    s = __hfma2(rw[4*(k)+0], hp[0], s); \
    s = __hfma2(rw[4*(k)+1], hp[1], s); \
    s = __hfma2(rw[4*(k)+2], hp[2], s); \
    s = __hfma2(rw[4*(k)+3], hp[3], s); }

#define CHUNK_FLUSH { float2 f2 = __half22float2(s); acc += f2.x; acc += f2.y; }

__global__ __launch_bounds__(640, 1) void k_lstm(int stage, float* __restrict__ outp,
                                                 int to_bctf) {
    __shared__ __align__(16) __half sHh[160];
    __shared__ float sG[640];
    const uint4* sH4 = (const uint4*)sHh;

    int b = blockIdx.x, g = blockIdx.y;
    int tid = threadIdx.x, p = tid;

    const __half2* gw = g_wh2 + (size_t)stage * 102400 + (size_t)g * 51200;

    // all 80 pairs into registers
    __half2 rw[80];
#pragma unroll
    for (int j = 0; j < 80; j++) rw[j] = gw[j * 640 + p];

    if (tid < 160) sHh[tid] = __float2half(0.f);
    __syncthreads();

    const float* xp = g_xproj + (size_t)b * 1000 * 1280 + g * 640 + p;
    float cst = 0.f;
    size_t obase = 0;
    if (tid < 160) {
        int d = g * 160 + tid;
        if (to_bctf) obase = (size_t)b * 320000 + (size_t)(d / 5) * 5000 + (d % 5);
        else         obase = (size_t)b * 320000 + d;
    }

    float xn = xp[0];

    for (int t = 0; t < 1000; t++) {
        float acc = xn;
        if (t + 1 < 1000) xn = xp[(size_t)(t + 1) * 1280];

        __half2 s;
        // 5 chunks of 32 rows (4 k-iters each), fp16 accumulate within chunk
        s = __float2half2_rn(0.f); ACC(0);  ACC(1);  ACC(2);  ACC(3);  CHUNK_FLUSH;
        s = __float2half2_rn(0.f); ACC(4);  ACC(5);  ACC(6);  ACC(7);  CHUNK_FLUSH;
        s = __float2half2_rn(0.f); ACC(8);  ACC(9);  ACC(10); ACC(11); CHUNK_FLUSH;
        s = __float2half2_rn(0.f); ACC(12); ACC(13); ACC(14); ACC(15); CHUNK_FLUSH;
        s = __float2half2_rn(0.f); ACC(16); ACC(17); ACC(18); ACC(19); CHUNK_FLUSH;

        sG[p] = acc;
        __syncthreads();

        if (tid < 160) {
            float gi = sG[tid], gf = sG[160 + tid], gg = sG[320 + tid], go = sG[480 + tid];
            float iv = 0.5f * tanh_ap(0.5f * gi) + 0.5f;
            float fv = 0.5f * tanh_ap(0.5f * gf) + 0.5f;
            float gv = tanh_ap(gg);
            float ov = 0.5f * tanh_ap(0.5f * go) + 0.5f;
            cst = fv * cst + iv * gv;
            float hv = ov * tanh_ap(cst);
            sHh[tid] = __float2half(hv);
            if (to_bctf) outp[obase + (size_t)t * 5] = hv;
            else         g_out1h[obase + (size_t)t * 320] = __float2half(hv);
        }
        __syncthreads();
    }
}

// ---------------- launcher ----------------
extern "C" void kernel_launch(void* const* d_in, const int* in_sizes, int n_in,
                              void* d_out, int out_size) {
    const float* input = (const float*)d_in[0];
    const float* Wih1  = (const float*)d_in[1];
    const float* Whh1  = (const float*)d_in[2];
    const float* b1    = (const float*)d_in[3];
    const float* Wih2  = (const float*)d_in[4];
    const float* Whh2  = (const float*)d_in[5];
    const float* b2    = (const float*)d_in[6];
    const int*   snd   = (const int*)d_in[7];
    float* out = (float*)d_out;

    cudaFuncSetAttribute(k_gemm, cudaFuncAttributeMaxDynamicSharedMemorySize, GEMM_SMEM);

    k_convert<<<(409600 + 255) / 256, 256>>>(Wih1, Wih2, Whh1, Whh2);
    k_transpose<<<dim3(64, 20), 256>>>(input);

    // stage 1
    k_gemm<<<dim3(500, 2, 2), 256, GEMM_SMEM>>>(0, b1);
    k_lstm<<<dim3(64, 2), 640>>>(0, out, 0);

    // stage 2
    k_gather<<<1000, 256>>>(snd);
    k_gemm<<<dim3(500, 2, 2), 256, GEMM_SMEM>>>(1, b2);
    k_lstm<<<dim3(64, 2), 640>>>(1, out, 1);
}

// round 13
// speedup vs baseline: 1.2085x; 1.2085x over previous
#include <cuda_runtime.h>
#include <cuda_fp16.h>

// B=64, T=1000, C=64, F=5, G=2, H=160, 4H=640, D=320, M=B*T=64000

// ---------------- static device scratch ----------------
__device__ __half  g_xT[20480000];     // [D=320][M=64000] k-major GEMM A
__device__ __half  g_out1h[20480000];  // [M][320] stage-1 hidden (fp16)
__device__ float   g_xproj[81920000];  // [M][1280] gate preacts (x@Wih + b), fp32
__device__ __half2 g_wh2[204800];      // [stage][g][80][640] pair-packed Whh: (W[2q][p],W[2q+1][p])
__device__ __half  g_wih[409600];      // [stage][g][160][640] fp16 Wih

// ---------------- helpers ----------------
__device__ __forceinline__ unsigned smem_u32(const void* p) {
    unsigned r;
    asm("{ .reg .u64 t; cvta.to.shared.u64 t, %1; cvt.u32.u64 %0, t; }" : "=r"(r) : "l"(p));
    return r;
}

__device__ __forceinline__ float tanh_ap(float x) {
    float r;
    asm("tanh.approx.f32 %0, %1;" : "=f"(r) : "f"(x));
    return r;
}

#define LDSM_X4T(r0,r1,r2,r3,a) \
    asm volatile("ldmatrix.sync.aligned.m8n8.x4.trans.shared.b16 {%0,%1,%2,%3}, [%4];" \
        : "=r"(r0),"=r"(r1),"=r"(r2),"=r"(r3) : "r"(a))

#define MMA16816(c0,c1,c2,c3,a0,a1,a2,a3,b0,b1) \
    asm volatile("mma.sync.aligned.m16n8k16.row.col.f32.f16.f16.f32 " \
        "{%0,%1,%2,%3}, {%4,%5,%6,%7}, {%8,%9}, {%0,%1,%2,%3};" \
        : "+f"(c0),"+f"(c1),"+f"(c2),"+f"(c3) \
        : "r"(a0),"r"(a1),"r"(a2),"r"(a3),"r"(b0),"r"(b1))

// ---------------- weight convert fp32 -> fp16 ----------------
// v5 packing: thread p owns gate column p; pairs (W[2q][p], W[2q+1][p]).
__global__ void k_convert(const float* __restrict__ Wi1, const float* __restrict__ Wi2,
                          const float* __restrict__ Wh1, const float* __restrict__ Wh2) {
    int i = blockIdx.x * blockDim.x + threadIdx.x;
    if (i >= 409600) return;
    if (i < 204800) g_wih[i] = __float2half(Wi1[i]);
    else            g_wih[i] = __float2half(Wi2[i - 204800]);
    if (i < 204800) {
        int st = i / 102400, r = i - st * 102400;   // per stage: g*51200 + q*640 + p
        int gg = r / 51200,  r2 = r - gg * 51200;
        int q = r2 / 640,    p = r2 - q * 640;
        const float* W = st ? Wh2 : Wh1;
        float a = W[gg * 102400 + (2 * q) * 640 + p];
        float b = W[gg * 102400 + (2 * q + 1) * 640 + p];
        g_wh2[i] = __halves2half2(__float2half(a), __float2half(b));
    }
}

// ---------------- transpose: input[B,C,T,F] -> g_xT[d][m] fp16 ----------------
__global__ __launch_bounds__(256) void k_transpose(const float* __restrict__ inp) {
    __shared__ __half sT[50 * 322];
    int b = blockIdx.x, t0 = blockIdx.y * 50;
    int tid = threadIdx.x;
    for (int i = tid; i < 8000; i += 256) {
        int ch = i / 125, j = i % 125;
        float2 v = *(const float2*)(inp + (size_t)(b * 64 + ch) * 5000 + t0 * 5 + j * 2);
        int e0 = j * 2, e1 = e0 + 1;
        sT[(e0 / 5) * 322 + ch * 5 + (e0 % 5)] = __float2half(v.x);
        sT[(e1 / 5) * 322 + ch * 5 + (e1 % 5)] = __float2half(v.y);
    }
    __syncthreads();
    for (int i = tid; i < 16000; i += 256) {
        int d = i / 50, t = i % 50;
        g_xT[(size_t)d * 64000 + (size_t)b * 1000 + t0 + t] = sT[t * 322 + d];
    }
}

// ---------------- gather: g_xT[d'][m] = out1h[m][snd[d']] ----------------
__global__ __launch_bounds__(256) void k_gather(const int* __restrict__ snd) {
    __shared__ __half sT[64 * 322];
    __shared__ int ssnd[320];
    int m0 = blockIdx.x * 64;
    int tid = threadIdx.x;
    for (int c = tid; c < 2560; c += 256) {
        int m = c / 40, ch = c % 40;
        uint4 v = *(const uint4*)(g_out1h + (size_t)(m0 + m) * 320 + ch * 8);
        unsigned* dst = (unsigned*)(sT + m * 322 + ch * 8);
        dst[0] = v.x; dst[1] = v.y; dst[2] = v.z; dst[3] = v.w;
    }
    for (int i = tid; i < 320; i += 256) ssnd[i] = snd[i];
    __syncthreads();
    for (int i = tid; i < 20480; i += 256) {
        int d = i / 64, m = i % 64;
        g_xT[(size_t)d * 64000 + m0 + m] = sT[m * 322 + ssnd[d]];
    }
}

// ---------------- tensor-core xproj GEMM ----------------
#define GEMM_SMEM (40960 + 102400)
__global__ __launch_bounds__(256) void k_gemm(int stage, const float* __restrict__ bias) {
    int g = blockIdx.z, nb = blockIdx.y * 320, m0 = blockIdx.x * 128;
    extern __shared__ __half gs[];
    __half* sA = gs;            // [160][128] halves, swizzled
    __half* sB = gs + 20480;    // [160][320] halves, swizzled
    unsigned sAu = smem_u32(sA), sBu = smem_u32(sB);
    int tid = threadIdx.x;
    const __half* Ag = g_xT + (size_t)g * 160 * 64000;
    const __half* Wg = g_wih + (size_t)stage * 204800 + (size_t)g * 102400;
    for (int c = tid; c < 2560; c += 256) {
        int k = c >> 4, cm = c & 15;
        uint4 v = *(const uint4*)(Ag + (size_t)k * 64000 + m0 + cm * 8);
        *(uint4*)((char*)sA + k * 256 + ((cm ^ (k & 7)) << 4)) = v;
    }
    for (int c = tid; c < 6400; c += 256) {
        int k = c / 40, ch = c % 40;
        uint4 v = *(const uint4*)(Wg + (size_t)k * 640 + nb + ch * 8);
        *(uint4*)((char*)sB + k * 640 + ((ch ^ (k & 7)) << 4)) = v;
    }
    __syncthreads();

    int w = tid >> 5, l = tid & 31;
    unsigned aAddr = sAu + ((l & 7) + ((l >> 4) << 3)) * 256
                         + (((w * 2 + ((l >> 3) & 1)) ^ (l & 7)) << 4);
    unsigned bRow = sBu + (l & 15) * 640;
    int bl = l & 7, bhi = l >> 4;

    for (int it = 0; it < 10; it++) {
        float acc[16];
#pragma unroll
        for (int i = 0; i < 16; i++) acc[i] = 0.f;
#pragma unroll
        for (int ks = 0; ks < 10; ks++) {
            unsigned a0, a1, a2, a3, b0, b1, b2, b3, b4, b5, b6, b7;
            LDSM_X4T(a0, a1, a2, a3, aAddr + ks * 16 * 256);
            int c0 = it * 4 + bhi;
            LDSM_X4T(b0, b1, b2, b3, bRow + ks * 16 * 640 + ((c0 ^ bl) << 4));
            int c1 = it * 4 + 2 + bhi;
            LDSM_X4T(b4, b5, b6, b7, bRow + ks * 16 * 640 + ((c1 ^ bl) << 4));
            MMA16816(acc[0], acc[1], acc[2], acc[3],  a0, a1, a2, a3, b0, b1);
            MMA16816(acc[4], acc[5], acc[6], acc[7],  a0, a1, a2, a3, b2, b3);
            MMA16816(acc[8], acc[9], acc[10], acc[11], a0, a1, a2, a3, b4, b5);
            MMA16816(acc[12], acc[13], acc[14], acc[15], a0, a1, a2, a3, b6, b7);
        }
        int row0 = m0 + w * 16 + (l >> 2);
        int col = g * 640 + nb + it * 32 + (l & 3) * 2;
#pragma unroll
        for (int ch = 0; ch < 4; ch++) {
            int c = col + ch * 8;
            float2 bv = *(const float2*)(bias + c);
            float2 v0 = { acc[ch * 4 + 0] + bv.x, acc[ch * 4 + 1] + bv.y };
            float2 v1 = { acc[ch * 4 + 2] + bv.x, acc[ch * 4 + 3] + bv.y };
            *(float2*)(g_xproj + (size_t)row0 * 1280 + c) = v0;
            *(float2*)(g_xproj + (size_t)(row0 + 8) * 1280 + c) = v1;
        }
    }
}

// ---------------- persistent recurrent LSTM (v8 = v5 + tanh + 5-chunk) ------
// grid (64 b, 2 g), 640 threads; thread p owns gate column p, ALL 160 rows.
// Pairs 0..55 (rows 0..111) in registers; pairs 56..79 streamed quad-packed
// from smem. h packed half[160]. Owner-only activation (5 warps) with MUFU.TANH.
#define LS_W   61440                 // 6 quads x 640 uint4
#define LS_H   LS_W                  // sH: half[160] = 320B, pad to 512
#define LS_G   (LS_W + 512)          // sG: 640 floats
#define LS_TOT (LS_G + 2560)

#define ACCR(k) { \
    uint4 hv = sH4[(k)]; \
    const __half2* hp = (const __half2*)&hv; \
    s = __hfma2(rw[4*(k)+0], hp[0], s); \
    s = __hfma2(rw[4*(k)+1], hp[1], s); \
    s = __hfma2(rw[4*(k)+2], hp[2], s); \
    s = __hfma2(rw[4*(k)+3], hp[3], s); }

#define ACCS(k) { \
    uint4 hv = sH4[(k)]; \
    const __half2* hp = (const __half2*)&hv; \
    uint4 wv = wqp[((k) - 14) * 640]; \
    s = __hfma2(*(__half2*)&wv.x, hp[0], s); \
    s = __hfma2(*(__half2*)&wv.y, hp[1], s); \
    s = __hfma2(*(__half2*)&wv.z, hp[2], s); \
    s = __hfma2(*(__half2*)&wv.w, hp[3], s); }

#define CHUNK_FLUSH { float2 f2 = __half22float2(s); acc += f2.x; acc += f2.y; }

__global__ __launch_bounds__(640, 1) void k_lstm(int stage, float* __restrict__ outp,
                                                 int to_bctf) {
    extern __shared__ char smem[];
    uint4*  sW4 = (uint4*)smem;
    __half* sHh = (__half*)(smem + LS_H);
    float*  sG  = (float*)(smem + LS_G);
    const uint4* sH4 = (const uint4*)sHh;

    int b = blockIdx.x, g = blockIdx.y;
    int tid = threadIdx.x, p = tid;

    const __half2* gw = g_wh2 + (size_t)stage * 102400 + (size_t)g * 51200;
    const unsigned* gwu = (const unsigned*)gw;

    // pairs 0..55 into registers
    __half2 rw[56];
#pragma unroll
    for (int j = 0; j < 56; j++) rw[j] = gw[j * 640 + p];

    // pairs 56..79 quad-packed into smem: sW4[k][p], k=0..5 covers pairs 56+4k..+3
    for (int i = tid; i < 3840; i += 640) {
        int k = i / 640, pp = i - k * 640;
        int q0 = 56 + 4 * k;
        uint4 v;
        v.x = gwu[(q0 + 0) * 640 + pp];
        v.y = gwu[(q0 + 1) * 640 + pp];
        v.z = gwu[(q0 + 2) * 640 + pp];
        v.w = gwu[(q0 + 3) * 640 + pp];
        sW4[k * 640 + pp] = v;
    }
    if (tid < 160) sHh[tid] = __float2half(0.f);
    __syncthreads();

    const float* xp = g_xproj + (size_t)b * 1000 * 1280 + g * 640 + p;
    float cst = 0.f;
    size_t obase = 0;
    if (tid < 160) {
        int d = g * 160 + tid;
        if (to_bctf) obase = (size_t)b * 320000 + (size_t)(d / 5) * 5000 + (d % 5);
        else         obase = (size_t)b * 320000 + d;
    }

    const uint4* wqp = sW4 + p;
    float xn = xp[0];

    for (int t = 0; t < 1000; t++) {
        float acc = xn;
        if (t + 1 < 1000) xn = xp[(size_t)(t + 1) * 1280];

        __half2 s;
        // 5 chunks of 32 rows (4 k-iters each), fp16 accumulate within chunk
        s = __float2half2_rn(0.f); ACCR(0);  ACCR(1);  ACCR(2);  ACCR(3);  CHUNK_FLUSH;
        s = __float2half2_rn(0.f); ACCR(4);  ACCR(5);  ACCR(6);  ACCR(7);  CHUNK_FLUSH;
        s = __float2half2_rn(0.f); ACCR(8);  ACCR(9);  ACCR(10); ACCR(11); CHUNK_FLUSH;
        s = __float2half2_rn(0.f); ACCR(12); ACCR(13); ACCS(14); ACCS(15); CHUNK_FLUSH;
        s = __float2half2_rn(0.f); ACCS(16); ACCS(17); ACCS(18); ACCS(19); CHUNK_FLUSH;

        sG[p] = acc;
        __syncthreads();

        if (tid < 160) {
            float gi = sG[tid], gf = sG[160 + tid], gg = sG[320 + tid], go = sG[480 + tid];
            float iv = 0.5f * tanh_ap(0.5f * gi) + 0.5f;
            float fv = 0.5f * tanh_ap(0.5f * gf) + 0.5f;
            float gv = tanh_ap(gg);
            float ov = 0.5f * tanh_ap(0.5f * go) + 0.5f;
            cst = fv * cst + iv * gv;
            float hv = ov * tanh_ap(cst);
            sHh[tid] = __float2half(hv);
            if (to_bctf) outp[obase + (size_t)t * 5] = hv;
            else         g_out1h[obase + (size_t)t * 320] = __float2half(hv);
        }
        __syncthreads();
    }
}

// ---------------- launcher ----------------
extern "C" void kernel_launch(void* const* d_in, const int* in_sizes, int n_in,
                              void* d_out, int out_size) {
    const float* input = (const float*)d_in[0];
    const float* Wih1  = (const float*)d_in[1];
    const float* Whh1  = (const float*)d_in[2];
    const float* b1    = (const float*)d_in[3];
    const float* Wih2  = (const float*)d_in[4];
    const float* Whh2  = (const float*)d_in[5];
    const float* b2    = (const float*)d_in[6];
    const int*   snd   = (const int*)d_in[7];
    float* out = (float*)d_out;

    cudaFuncSetAttribute(k_gemm, cudaFuncAttributeMaxDynamicSharedMemorySize, GEMM_SMEM);
    cudaFuncSetAttribute(k_lstm, cudaFuncAttributeMaxDynamicSharedMemorySize, LS_TOT);

    k_convert<<<(409600 + 255) / 256, 256>>>(Wih1, Wih2, Whh1, Whh2);
    k_transpose<<<dim3(64, 20), 256>>>(input);

    // stage 1
    k_gemm<<<dim3(500, 2, 2), 256, GEMM_SMEM>>>(0, b1);
    k_lstm<<<dim3(64, 2), 640, LS_TOT>>>(0, out, 0);

    // stage 2
    k_gather<<<1000, 256>>>(snd);
    k_gemm<<<dim3(500, 2, 2), 256, GEMM_SMEM>>>(1, b2);
    k_lstm<<<dim3(64, 2), 640, LS_TOT>>>(1, out, 1);
}

// round 15
// speedup vs baseline: 1.2618x; 1.0441x over previous
#include <cuda_runtime.h>
#include <cuda_fp16.h>

// B=64, T=1000, C=64, F=5, G=2, H=160, 4H=640, D=320, M=B*T=64000

// ---------------- static device scratch ----------------
__device__ __half  g_xT[20480000];     // [D=320][M=64000] k-major stage-1 GEMM A
__device__ __half  g_out1hT[20480000]; // [320][64000] stage-1 hidden, TRANSPOSED (row d, col m)
__device__ float   g_xproj[81920000];  // [M][1280] gate preacts (x@Wih + b), fp32
__device__ __half2 g_wh2[204800];      // [stage][g][80][640] pair-packed Whh, GATE-INTERLEAVED cols
__device__ __half  g_wih[409600];      // [stage][g][160][640] fp16 Wih
__device__ int     g_rowmap[640];      // [stage][g*160+k] -> A row (stage0: identity, stage1: snd)

// ---------------- helpers ----------------
__device__ __forceinline__ unsigned smem_u32(const void* p) {
    unsigned r;
    asm("{ .reg .u64 t; cvta.to.shared.u64 t, %1; cvt.u32.u64 %0, t; }" : "=r"(r) : "l"(p));
    return r;
}

__device__ __forceinline__ float tanh_ap(float x) {
    float r;
    asm("tanh.approx.f32 %0, %1;" : "=f"(r) : "f"(x));
    return r;
}

#define LDSM_X4T(r0,r1,r2,r3,a) \
    asm volatile("ldmatrix.sync.aligned.m8n8.x4.trans.shared.b16 {%0,%1,%2,%3}, [%4];" \
        : "=r"(r0),"=r"(r1),"=r"(r2),"=r"(r3) : "r"(a))

#define MMA16816(c0,c1,c2,c3,a0,a1,a2,a3,b0,b1) \
    asm volatile("mma.sync.aligned.m16n8k16.row.col.f32.f16.f16.f32 " \
        "{%0,%1,%2,%3}, {%4,%5,%6,%7}, {%8,%9}, {%0,%1,%2,%3};" \
        : "+f"(c0),"+f"(c1),"+f"(c2),"+f"(c3) \
        : "r"(a0),"r"(a1),"r"(a2),"r"(a3),"r"(b0),"r"(b1))

// ---------------- weight convert fp32 -> fp16 ----------------
// Whh pairs with gate-interleaved column perm: thread p owns gate (p&3) of
// h-col (p>>2) -> source col j = (p&3)*160 + (p>>2). Also builds g_rowmap.
__global__ void k_convert(const float* __restrict__ Wi1, const float* __restrict__ Wi2,
                          const float* __restrict__ Wh1, const float* __restrict__ Wh2,
                          const int* __restrict__ snd) {
    int i = blockIdx.x * blockDim.x + threadIdx.x;
    if (i >= 409600) return;
    if (i < 320) { g_rowmap[i] = i; g_rowmap[320 + i] = snd[i]; }
    if (i < 204800) g_wih[i] = __float2half(Wi1[i]);
    else            g_wih[i] = __float2half(Wi2[i - 204800]);
    if (i < 204800) {
        int st = i / 102400, r = i - st * 102400;   // per stage: g*51200 + q*640 + p
        int gg = r / 51200,  r2 = r - gg * 51200;
        int q = r2 / 640,    p = r2 - q * 640;
        int j = (p & 3) * 160 + (p >> 2);           // gate-interleaved source column
        const float* W = st ? Wh2 : Wh1;
        float a = W[gg * 102400 + (2 * q) * 640 + j];
        float b = W[gg * 102400 + (2 * q + 1) * 640 + j];
        g_wh2[i] = __halves2half2(__float2half(a), __float2half(b));
    }
}

// ---------------- transpose: input[B,C,T,F] -> g_xT[d][m] fp16 ----------------
__global__ __launch_bounds__(256) void k_transpose(const float* __restrict__ inp) {
    __shared__ __half sT[50 * 322];
    int b = blockIdx.x, t0 = blockIdx.y * 50;
    int tid = threadIdx.x;
    for (int i = tid; i < 8000; i += 256) {
        int ch = i / 125, j = i % 125;
        float2 v = *(const float2*)(inp + (size_t)(b * 64 + ch) * 5000 + t0 * 5 + j * 2);
        int e0 = j * 2, e1 = e0 + 1;
        sT[(e0 / 5) * 322 + ch * 5 + (e0 % 5)] = __float2half(v.x);
        sT[(e1 / 5) * 322 + ch * 5 + (e1 % 5)] = __float2half(v.y);
    }
    __syncthreads();
    for (int i = tid; i < 16000; i += 256) {
        int d = i / 50, t = i % 50;
        g_xT[(size_t)d * 64000 + (size_t)b * 1000 + t0 + t] = sT[t * 322 + d];
    }
}

// ---------------- tensor-core xproj GEMM (v2: N=160 tile, 2 CTAs/SM) --------
// A rows read through g_rowmap (stage1 = snd permutation -> gather eliminated).
// B tile rows padded to 384B so xor-swizzle index range [0,24) fits.
#define GEMM_SMEM (40960 + 61440)
__global__ __launch_bounds__(256, 2) void k_gemm(int stage, const float* __restrict__ bias) {
    int g = blockIdx.z, nb = blockIdx.y * 160, m0 = blockIdx.x * 128;
    extern __shared__ __half gs[];
    __half* sA = gs;                 // [160][128] halves, row 256B, swizzled
    __half* sB = gs + 20480;         // [160] rows x 384B pitch, swizzled
    unsigned sAu = smem_u32(sA), sBu = smem_u32(sB);
    int tid = threadIdx.x;
    const __half* Abase = stage ? g_out1hT : g_xT;
    const int* rmap = g_rowmap + stage * 320 + g * 160;
    const __half* Wg = g_wih + (size_t)stage * 204800 + (size_t)g * 102400;

    for (int c = tid; c < 2560; c += 256) {
        int k = c >> 4, cm = c & 15;
        int row = __ldg(rmap + k);
        uint4 v = *(const uint4*)(Abase + (size_t)row * 64000 + m0 + cm * 8);
        *(uint4*)((char*)sA + k * 256 + ((cm ^ (k & 7)) << 4)) = v;
    }
    for (int c = tid; c < 3200; c += 256) {
        int k = c / 20, ch = c % 20;
        uint4 v = *(const uint4*)(Wg + (size_t)k * 640 + nb + ch * 8);
        *(uint4*)((char*)sB + k * 384 + ((ch ^ (k & 7)) << 4)) = v;
    }
    __syncthreads();

    int w = tid >> 5, l = tid & 31;
    unsigned aAddr = sAu + ((l & 7) + ((l >> 4) << 3)) * 256
                         + (((w * 2 + ((l >> 3) & 1)) ^ (l & 7)) << 4);
    unsigned bRow = sBu + (l & 15) * 384;
    int bl = l & 7, bhi = l >> 4;

    for (int it = 0; it < 5; it++) {
        float acc[16];
#pragma unroll
        for (int i = 0; i < 16; i++) acc[i] = 0.f;
#pragma unroll
        for (int ks = 0; ks < 10; ks++) {
            unsigned a0, a1, a2, a3, b0, b1, b2, b3, b4, b5, b6, b7;
            LDSM_X4T(a0, a1, a2, a3, aAddr + ks * 16 * 256);
            int c0 = it * 4 + bhi;
            LDSM_X4T(b0, b1, b2, b3, bRow + ks * 16 * 384 + ((c0 ^ bl) << 4));
            int c1 = it * 4 + 2 + bhi;
            LDSM_X4T(b4, b5, b6, b7, bRow + ks * 16 * 384 + ((c1 ^ bl) << 4));
            MMA16816(acc[0], acc[1], acc[2], acc[3],  a0, a1, a2, a3, b0, b1);
            MMA16816(acc[4], acc[5], acc[6], acc[7],  a0, a1, a2, a3, b2, b3);
            MMA16816(acc[8], acc[9], acc[10], acc[11], a0, a1, a2, a3, b4, b5);
            MMA16816(acc[12], acc[13], acc[14], acc[15], a0, a1, a2, a3, b6, b7);
        }
        int row0 = m0 + w * 16 + (l >> 2);
        int col = g * 640 + nb + it * 32 + (l & 3) * 2;
#pragma unroll
        for (int ch = 0; ch < 4; ch++) {
            int c = col + ch * 8;
            float2 bv = *(const float2*)(bias + c);
            float2 v0 = { acc[ch * 4 + 0] + bv.x, acc[ch * 4 + 1] + bv.y };
            float2 v1 = { acc[ch * 4 + 2] + bv.x, acc[ch * 4 + 3] + bv.y };
            *(float2*)(g_xproj + (size_t)row0 * 1280 + c) = v0;
            *(float2*)(g_xproj + (size_t)(row0 + 8) * 1280 + c) = v1;
        }
    }
}

// ---------------- persistent recurrent LSTM (v9) ----------------
// grid (64 b, 2 g), 640 threads; thread p computes gate (p&3) of h-col (p>>2)
// (quad-gate column order; weights/xproj columns pre-permuted). Pairs 0..55
// in registers; pairs 56..79 streamed quad-packed from smem. Owner (tid<160)
// reads its 4 gate preacts as ONE float4 and does the MUFU.TANH tail.
// Stage-1 output written TRANSPOSED into g_out1hT (gather kernel eliminated).
#define LS_W   61440                 // 6 quads x 640 uint4
#define LS_H   LS_W                  // sH: half[160] = 320B, pad to 512
#define LS_G   (LS_W + 512)          // sG: 640 floats (quad-gate order)
#define LS_TOT (LS_G + 2560)

#define ACCR(k) { \
    uint4 hv = sH4[(k)]; \
    const __half2* hp = (const __half2*)&hv; \
    s = __hfma2(rw[4*(k)+0], hp[0], s); \
    s = __hfma2(rw[4*(k)+1], hp[1], s); \
    s = __hfma2(rw[4*(k)+2], hp[2], s); \
    s = __hfma2(rw[4*(k)+3], hp[3], s); }

#define ACCS(k) { \
    uint4 hv = sH4[(k)]; \
    const __half2* hp = (const __half2*)&hv; \
    uint4 wv = wqp[((k) - 14) * 640]; \
    s = __hfma2(*(__half2*)&wv.x, hp[0], s); \
    s = __hfma2(*(__half2*)&wv.y, hp[1], s); \
    s = __hfma2(*(__half2*)&wv.z, hp[2], s); \
    s = __hfma2(*(__half2*)&wv.w, hp[3], s); }

#define CHUNK_FLUSH { float2 f2 = __half22float2(s); acc += f2.x; acc += f2.y; }

__global__ __launch_bounds__(640, 1) void k_lstm(int stage, float* __restrict__ outp,
                                                 int to_bctf) {
    extern __shared__ char smem[];
    uint4*  sW4 = (uint4*)smem;
    __half* sHh = (__half*)(smem + LS_H);
    float*  sG  = (float*)(smem + LS_G);
    const uint4*  sH4 = (const uint4*)sHh;
    const float4* sG4 = (const float4*)sG;

    int b = blockIdx.x, g = blockIdx.y;
    int tid = threadIdx.x, p = tid;
    int jcol = (p & 3) * 160 + (p >> 2);   // logical gate column (permuted)

    const __half2* gw = g_wh2 + (size_t)stage * 102400 + (size_t)g * 51200;
    const unsigned* gwu = (const unsigned*)gw;

    // pairs 0..55 into registers
    __half2 rw[56];
#pragma unroll
    for (int j = 0; j < 56; j++) rw[j] = gw[j * 640 + p];

    // pairs 56..79 quad-packed into smem
    for (int i = tid; i < 3840; i += 640) {
        int k = i / 640, pp = i - k * 640;
        int q0 = 56 + 4 * k;
        uint4 v;
        v.x = gwu[(q0 + 0) * 640 + pp];
        v.y = gwu[(q0 + 1) * 640 + pp];
        v.z = gwu[(q0 + 2) * 640 + pp];
        v.w = gwu[(q0 + 3) * 640 + pp];
        sW4[k * 640 + pp] = v;
    }
    if (tid < 160) sHh[tid] = __float2half(0.f);
    __syncthreads();

    const float* xp = g_xproj + (size_t)b * 1000 * 1280 + g * 640 + jcol;
    float cst = 0.f;
    size_t obase = 0;
    if (tid < 160) {
        int d = g * 160 + tid;
        if (to_bctf) obase = (size_t)b * 320000 + (size_t)(d / 5) * 5000 + (d % 5);
        else         obase = (size_t)d * 64000 + (size_t)b * 1000;   // transposed
    }

    const uint4* wqp = sW4 + p;
    float xn = xp[0];

    for (int t = 0; t < 1000; t++) {
        float acc = xn;
        if (t + 1 < 1000) xn = xp[(size_t)(t + 1) * 1280];

        __half2 s;
        // 5 chunks of 32 rows (4 k-iters each), fp16 accumulate within chunk
        s = __float2half2_rn(0.f); ACCR(0);  ACCR(1);  ACCR(2);  ACCR(3);  CHUNK_FLUSH;
        s = __float2half2_rn(0.f); ACCR(4);  ACCR(5);  ACCR(6);  ACCR(7);  CHUNK_FLUSH;
        s = __float2half2_rn(0.f); ACCR(8);  ACCR(9);  ACCR(10); ACCR(11); CHUNK_FLUSH;
        s = __float2half2_rn(0.f); ACCR(12); ACCR(13); ACCS(14); ACCS(15); CHUNK_FLUSH;
        s = __float2half2_rn(0.f); ACCS(16); ACCS(17); ACCS(18); ACCS(19); CHUNK_FLUSH;

        sG[p] = acc;
        __syncthreads();

        if (tid < 160) {
            float4 gv4 = sG4[tid];   // (i, f, g, o) preacts of column tid
            float iv = 0.5f * tanh_ap(0.5f * gv4.x) + 0.5f;
            float fv = 0.5f * tanh_ap(0.5f * gv4.y) + 0.5f;
            float gg = tanh_ap(gv4.z);
            float ov = 0.5f * tanh_ap(0.5f * gv4.w) + 0.5f;
            cst = fv * cst + iv * gg;
            float hv = ov * tanh_ap(cst);
            sHh[tid] = __float2half(hv);
            if (to_bctf) outp[obase + (size_t)t * 5] = hv;
            else         g_out1hT[obase + t] = __float2half(hv);
        }
        __syncthreads();
    }
}

// ---------------- launcher ----------------
extern "C" void kernel_launch(void* const* d_in, const int* in_sizes, int n_in,
                              void* d_out, int out_size) {
    const float* input = (const float*)d_in[0];
    const float* Wih1  = (const float*)d_in[1];
    const float* Whh1  = (const float*)d_in[2];
    const float* b1    = (const float*)d_in[3];
    const float* Wih2  = (const float*)d_in[4];
    const float* Whh2  = (const float*)d_in[5];
    const float* b2    = (const float*)d_in[6];
    const int*   snd   = (const int*)d_in[7];
    float* out = (float*)d_out;

    cudaFuncSetAttribute(k_gemm, cudaFuncAttributeMaxDynamicSharedMemorySize, GEMM_SMEM);
    cudaFuncSetAttribute(k_lstm, cudaFuncAttributeMaxDynamicSharedMemorySize, LS_TOT);

    k_convert<<<(409600 + 255) / 256, 256>>>(Wih1, Wih2, Whh1, Whh2, snd);
    k_transpose<<<dim3(64, 20), 256>>>(input);

    // stage 1
    k_gemm<<<dim3(500, 4, 2), 256, GEMM_SMEM>>>(0, b1);
    k_lstm<<<dim3(64, 2), 640, LS_TOT>>>(0, out, 0);

    // stage 2 (A rows gathered via g_rowmap inside k_gemm — no gather kernel)
    k_gemm<<<dim3(500, 4, 2), 256, GEMM_SMEM>>>(1, b2);
    k_lstm<<<dim3(64, 2), 640, LS_TOT>>>(1, out, 1);
}